// round 9
// baseline (speedup 1.0000x reference)
#include <cuda_runtime.h>
#include <cuda_bf16.h>
#include <math.h>
#include <stdint.h>

#define NN 100000
#define NE 3200000

// ---------------- scratch ----------------
__device__ float g_s[(size_t)NN * 256];   // buffer A (s0, then h1, then logits)
__device__ float g_h[(size_t)NN * 256];   // buffer B (s1, then s2)
__device__ __nv_bfloat16 g_ah[(size_t)NN * 256];   // activation hi (layer-1 input)
__device__ __nv_bfloat16 g_al[(size_t)NN * 256];   // activation lo
__device__ __nv_bfloat16 g_w0h[512 * 256], g_w0l[512 * 256];   // [N][K] n-major
__device__ __nv_bfloat16 g_w1h[256 * 128], g_w1l[256 * 128];
__device__ int   g_deg[NN];
__device__ int   g_rowptr[NN + 1];
__device__ int   g_cursor[NN];
__device__ int   g_srcs[NE];
__device__ float g_vals[NE];

// ---------------- helpers ----------------
__device__ __forceinline__ uint32_t smem_u32(const void* p) {
    uint32_t a;
    asm("{ .reg .u64 t; cvta.to.shared.u64 t, %1; cvt.u32.u64 %0, t; }" : "=r"(a) : "l"(p));
    return a;
}

__device__ __forceinline__ void split2(float a, float b, uint32_t& hi, uint32_t& lo) {
    __nv_bfloat16 ah = __float2bfloat16(a), bh = __float2bfloat16(b);
    float ar = a - __bfloat162float(ah);
    float br = b - __bfloat162float(bh);
    __nv_bfloat16 al = __float2bfloat16(ar), bl = __float2bfloat16(br);
    hi = (uint32_t)__bfloat16_as_ushort(ah) | ((uint32_t)__bfloat16_as_ushort(bh) << 16);
    lo = (uint32_t)__bfloat16_as_ushort(al) | ((uint32_t)__bfloat16_as_ushort(bl) << 16);
}

__device__ __forceinline__ void ldm4(uint32_t* r, uint32_t addr) {
    asm volatile("ldmatrix.sync.aligned.m8n8.x4.shared.b16 {%0,%1,%2,%3}, [%4];"
                 : "=r"(r[0]), "=r"(r[1]), "=r"(r[2]), "=r"(r[3]) : "r"(addr));
}

__device__ __forceinline__ void mma16816(float* c, const uint32_t* a, uint32_t b0, uint32_t b1) {
    asm volatile(
        "mma.sync.aligned.m16n8k16.row.col.f32.bf16.bf16.f32 "
        "{%0,%1,%2,%3}, {%4,%5,%6,%7}, {%8,%9}, {%0,%1,%2,%3};"
        : "+f"(c[0]), "+f"(c[1]), "+f"(c[2]), "+f"(c[3])
        : "r"(a[0]), "r"(a[1]), "r"(a[2]), "r"(a[3]), "r"(b0), "r"(b1));
}

// ---------------- CSR build ----------------
__global__ void k_zero_deg() {
    int i = blockIdx.x * blockDim.x + threadIdx.x;
    if (i < NN) g_deg[i] = 0;
}
__global__ void k_hist(const int* __restrict__ dst) {
    int e = blockIdx.x * blockDim.x + threadIdx.x;
    if (e < NE) atomicAdd(&g_deg[dst[e]], 1);
}
__global__ void k_scan() {
    __shared__ int ssum[1024];
    const int t = threadIdx.x;
    const int CH = (NN + 1023) / 1024;
    int s0 = t * CH, s1 = s0 + CH; if (s1 > NN) s1 = NN;
    int sum = 0;
    for (int i = s0; i < s1; i++) sum += g_deg[i];
    ssum[t] = sum;
    __syncthreads();
    for (int off = 1; off < 1024; off <<= 1) {
        int v = (t >= off) ? ssum[t - off] : 0;
        __syncthreads();
        ssum[t] += v;
        __syncthreads();
    }
    int run = (t == 0) ? 0 : ssum[t - 1];
    for (int i = s0; i < s1; i++) { g_rowptr[i] = run; g_cursor[i] = run; run += g_deg[i]; }
    if (t == 1023) g_rowptr[NN] = ssum[1023];
}
__global__ void k_scatter(const int* __restrict__ src, const int* __restrict__ dst,
                          const float* __restrict__ val) {
    int e = blockIdx.x * blockDim.x + threadIdx.x;
    if (e >= NE) return;
    int d = dst[e];
    int p = atomicAdd(&g_cursor[d], 1);
    g_srcs[p] = src[e];
    g_vals[p] = val[e];
}

// ---------------- weight converter: W [K][N] fp32 -> [N][K] bf16 hi/lo ----------------
__global__ void k_cvt_w(const float* __restrict__ W, __nv_bfloat16* __restrict__ wh,
                        __nv_bfloat16* __restrict__ wl, int K, int N) {
    int idx = blockIdx.x * blockDim.x + threadIdx.x;
    if (idx >= N * K) return;
    int n = idx / K, k = idx % K;
    float v = W[(size_t)k * N + n];
    __nv_bfloat16 h = __float2bfloat16(v);
    float r = v - __bfloat162float(h);
    wh[idx] = h;
    wl[idx] = __float2bfloat16(r);
}

// ---------------- tensor-core GEMM (fp32 A, fused split): C cols [n_base, n_base+128) ----------------
// A: [M][K] fp32. B: [N][K] bf16 hi/lo. C row stride N. grid (1, M/128).
__global__ void __launch_bounds__(256, 2)
k_mma_gemm_f32a(const float* __restrict__ A,
                const __nv_bfloat16* __restrict__ Bh, const __nv_bfloat16* __restrict__ Bl,
                const float* __restrict__ bias, float* __restrict__ C,
                int M, int K, int N, int n_base) {
    __shared__ __nv_bfloat16 sAh[128][40];
    __shared__ __nv_bfloat16 sAl[128][40];
    __shared__ __nv_bfloat16 sBh[128][40];
    __shared__ __nv_bfloat16 sBl[128][40];

    const int tid = threadIdx.x;
    const int wid = tid >> 5, lane = tid & 31;
    const int m0 = blockIdx.y * 128;
    const int n0 = n_base + blockIdx.x * 128;
    const int wm = wid >> 2;
    const int wn = wid & 3;

    int lrow[2], lq[2];
#pragma unroll
    for (int it = 0; it < 2; it++) {
        int idx = it * 256 + tid;
        lrow[it] = idx >> 2;
        lq[it] = idx & 3;
    }

    float acc[4][4][4];
#pragma unroll
    for (int a = 0; a < 4; a++)
#pragma unroll
        for (int b = 0; b < 4; b++)
#pragma unroll
            for (int c = 0; c < 4; c++) acc[a][b][c] = 0.f;

    float4 fA[2][2];
    uint4 pBh[2], pBl[2];

    auto fetch = [&](int ch) {
        const int k0 = ch * 32;
#pragma unroll
        for (int it = 0; it < 2; it++) {
            int row = lrow[it], q = lq[it];
            if (m0 + row < M) {
                const float* p = &A[(size_t)(m0 + row) * K + k0 + q * 8];
                fA[it][0] = *(const float4*)p;
                fA[it][1] = *(const float4*)(p + 4);
            } else {
                fA[it][0] = make_float4(0.f, 0.f, 0.f, 0.f);
                fA[it][1] = make_float4(0.f, 0.f, 0.f, 0.f);
            }
            size_t offb = (size_t)(n0 + row) * K + k0 + q * 8;
            pBh[it] = *(const uint4*)&Bh[offb];
            pBl[it] = *(const uint4*)&Bl[offb];
        }
    };
    auto commit = [&]() {
#pragma unroll
        for (int it = 0; it < 2; it++) {
            int row = lrow[it], q = lq[it];
            uint4 vh, vl;
            split2(fA[it][0].x, fA[it][0].y, vh.x, vl.x);
            split2(fA[it][0].z, fA[it][0].w, vh.y, vl.y);
            split2(fA[it][1].x, fA[it][1].y, vh.z, vl.z);
            split2(fA[it][1].z, fA[it][1].w, vh.w, vl.w);
            *(uint4*)&sAh[row][q * 8] = vh;
            *(uint4*)&sAl[row][q * 8] = vl;
            *(uint4*)&sBh[row][q * 8] = pBh[it];
            *(uint4*)&sBl[row][q * 8] = pBl[it];
        }
    };

    const int nch = K / 32;
    fetch(0);
    commit();

    for (int ch = 0; ch < nch; ch++) {
        __syncthreads();
        if (ch + 1 < nch) fetch(ch + 1);

#pragma unroll
        for (int kk = 0; kk < 32; kk += 16) {
            const int r = lane & 15;
            const int koff = (lane >> 4) << 3;
            uint32_t bhf[2][4], blf[2][4];
#pragma unroll
            for (int nt = 0; nt < 2; nt++) {
                ldm4(bhf[nt], smem_u32(&sBh[wn * 32 + nt * 16 + r][kk + koff]));
                ldm4(blf[nt], smem_u32(&sBl[wn * 32 + nt * 16 + r][kk + koff]));
            }
#pragma unroll
            for (int mt = 0; mt < 4; mt++) {
                uint32_t af[4];
                ldm4(af, smem_u32(&sAh[wm * 64 + mt * 16 + r][kk + koff]));
#pragma unroll
                for (int j = 0; j < 4; j++) {
                    mma16816(acc[mt][j], af, bhf[j >> 1][j & 1], bhf[j >> 1][2 + (j & 1)]);
                    mma16816(acc[mt][j], af, blf[j >> 1][j & 1], blf[j >> 1][2 + (j & 1)]);
                }
            }
#pragma unroll
            for (int mt = 0; mt < 4; mt++) {
                uint32_t af[4];
                ldm4(af, smem_u32(&sAl[wm * 64 + mt * 16 + r][kk + koff]));
#pragma unroll
                for (int j = 0; j < 4; j++)
                    mma16816(acc[mt][j], af, bhf[j >> 1][j & 1], bhf[j >> 1][2 + (j & 1)]);
            }
        }
        __syncthreads();
        if (ch + 1 < nch) commit();
    }

    const int rbase = m0 + wm * 64 + (lane >> 2);
    const int cbase = n0 + wn * 32 + (lane & 3) * 2;
#pragma unroll
    for (int mt = 0; mt < 4; mt++) {
        int m = rbase + mt * 16;
#pragma unroll
        for (int j = 0; j < 4; j++) {
            int c = cbase + j * 8;
            float bv0 = bias[c], bv1 = bias[c + 1];
            if (m < M) {
                float2 o = make_float2(acc[mt][j][0] + bv0, acc[mt][j][1] + bv1);
                *(float2*)&C[(size_t)m * N + c] = o;
            }
            if (m + 8 < M) {
                float2 o = make_float2(acc[mt][j][2] + bv0, acc[mt][j][3] + bv1);
                *(float2*)&C[(size_t)(m + 8) * N + c] = o;
            }
        }
    }
}

// ---------------- tensor-core GEMM (bf16 hi/lo A), K-chunked with optional accumulate ----------------
// Processes K range [k_base, k_base + Kproc) of rows with stride Kstride.
// accum==0: C = acc + bias ; accum==1: C += acc.
__global__ void __launch_bounds__(256, 2)
k_mma_gemm(const __nv_bfloat16* __restrict__ Ah, const __nv_bfloat16* __restrict__ Al,
           const __nv_bfloat16* __restrict__ Bh, const __nv_bfloat16* __restrict__ Bl,
           const float* __restrict__ bias, float* __restrict__ C,
           int M, int Kstride, int k_base, int Kproc, int N, int accum) {
    __shared__ __nv_bfloat16 sAh[128][40];
    __shared__ __nv_bfloat16 sAl[128][40];
    __shared__ __nv_bfloat16 sBh[128][40];
    __shared__ __nv_bfloat16 sBl[128][40];

    const int tid = threadIdx.x;
    const int wid = tid >> 5, lane = tid & 31;
    const int m0 = blockIdx.y * 128;
    const int n0 = blockIdx.x * 128;
    const int wm = wid >> 2;
    const int wn = wid & 3;

    int lrow[2], lq[2];
#pragma unroll
    for (int it = 0; it < 2; it++) {
        int idx = it * 256 + tid;
        lrow[it] = idx >> 2;
        lq[it] = idx & 3;
    }

    float acc[4][4][4];
#pragma unroll
    for (int a = 0; a < 4; a++)
#pragma unroll
        for (int b = 0; b < 4; b++)
#pragma unroll
            for (int c = 0; c < 4; c++) acc[a][b][c] = 0.f;

    uint4 pAh[2], pAl[2], pBh[2], pBl[2];

    auto fetch = [&](int ch) {
        const int k0 = k_base + ch * 32;
#pragma unroll
        for (int it = 0; it < 2; it++) {
            int row = lrow[it], q = lq[it];
            if (m0 + row < M) {
                size_t off = (size_t)(m0 + row) * Kstride + k0 + q * 8;
                pAh[it] = *(const uint4*)&Ah[off];
                pAl[it] = *(const uint4*)&Al[off];
            } else {
                pAh[it] = make_uint4(0, 0, 0, 0);
                pAl[it] = make_uint4(0, 0, 0, 0);
            }
            size_t offb = (size_t)(n0 + row) * Kstride + k0 + q * 8;
            pBh[it] = *(const uint4*)&Bh[offb];
            pBl[it] = *(const uint4*)&Bl[offb];
        }
    };
    auto commit = [&]() {
#pragma unroll
        for (int it = 0; it < 2; it++) {
            int row = lrow[it], q = lq[it];
            *(uint4*)&sAh[row][q * 8] = pAh[it];
            *(uint4*)&sAl[row][q * 8] = pAl[it];
            *(uint4*)&sBh[row][q * 8] = pBh[it];
            *(uint4*)&sBl[row][q * 8] = pBl[it];
        }
    };

    const int nch = Kproc / 32;
    fetch(0);
    commit();

    for (int ch = 0; ch < nch; ch++) {
        __syncthreads();
        if (ch + 1 < nch) fetch(ch + 1);

#pragma unroll
        for (int kk = 0; kk < 32; kk += 16) {
            const int r = lane & 15;
            const int koff = (lane >> 4) << 3;
            uint32_t bhf[2][4], blf[2][4];
#pragma unroll
            for (int nt = 0; nt < 2; nt++) {
                ldm4(bhf[nt], smem_u32(&sBh[wn * 32 + nt * 16 + r][kk + koff]));
                ldm4(blf[nt], smem_u32(&sBl[wn * 32 + nt * 16 + r][kk + koff]));
            }
#pragma unroll
            for (int mt = 0; mt < 4; mt++) {
                uint32_t af[4];
                ldm4(af, smem_u32(&sAh[wm * 64 + mt * 16 + r][kk + koff]));
#pragma unroll
                for (int j = 0; j < 4; j++) {
                    mma16816(acc[mt][j], af, bhf[j >> 1][j & 1], bhf[j >> 1][2 + (j & 1)]);
                    mma16816(acc[mt][j], af, blf[j >> 1][j & 1], blf[j >> 1][2 + (j & 1)]);
                }
            }
#pragma unroll
            for (int mt = 0; mt < 4; mt++) {
                uint32_t af[4];
                ldm4(af, smem_u32(&sAl[wm * 64 + mt * 16 + r][kk + koff]));
#pragma unroll
                for (int j = 0; j < 4; j++)
                    mma16816(acc[mt][j], af, bhf[j >> 1][j & 1], bhf[j >> 1][2 + (j & 1)]);
            }
        }
        __syncthreads();
        if (ch + 1 < nch) commit();
    }

    const int rbase = m0 + wm * 64 + (lane >> 2);
    const int cbase = n0 + wn * 32 + (lane & 3) * 2;
#pragma unroll
    for (int mt = 0; mt < 4; mt++) {
        int m = rbase + mt * 16;
#pragma unroll
        for (int j = 0; j < 4; j++) {
            int c = cbase + j * 8;
            if (accum) {
                if (m < M) {
                    float2 old = *(float2*)&C[(size_t)m * N + c];
                    float2 o = make_float2(acc[mt][j][0] + old.x, acc[mt][j][1] + old.y);
                    *(float2*)&C[(size_t)m * N + c] = o;
                }
                if (m + 8 < M) {
                    float2 old = *(float2*)&C[(size_t)(m + 8) * N + c];
                    float2 o = make_float2(acc[mt][j][2] + old.x, acc[mt][j][3] + old.y);
                    *(float2*)&C[(size_t)(m + 8) * N + c] = o;
                }
            } else {
                float bv0 = bias[c], bv1 = bias[c + 1];
                if (m < M) {
                    float2 o = make_float2(acc[mt][j][0] + bv0, acc[mt][j][1] + bv1);
                    *(float2*)&C[(size_t)m * N + c] = o;
                }
                if (m + 8 < M) {
                    float2 o = make_float2(acc[mt][j][2] + bv0, acc[mt][j][3] + bv1);
                    *(float2*)&C[(size_t)(m + 8) * N + c] = o;
                }
            }
        }
    }
}

// ---------------- SIMT GEMM (layer 2: K=128, N=40) ----------------
template <int BM, int BN, int BK, int TM, int TN>
__global__ void __launch_bounds__((BM / TM) * (BN / TN))
k_gemm(const float* __restrict__ A, const float* __restrict__ W,
       const float* __restrict__ bias, float* __restrict__ C,
       int M, int K, int N) {
    __shared__ float As[BK][BM];
    __shared__ float Bs[BK][BN];
    constexpr int NTH = (BM / TM) * (BN / TN);
    const int tid = threadIdx.y * blockDim.x + threadIdx.x;
    const int m0 = blockIdx.y * BM;
    const int n0 = blockIdx.x * BN;

    float acc[TM][TN];
#pragma unroll
    for (int i = 0; i < TM; i++)
#pragma unroll
        for (int j = 0; j < TN; j++) acc[i][j] = 0.0f;

    for (int k0 = 0; k0 < K; k0 += BK) {
#pragma unroll
        for (int i = tid; i < BM * BK / 4; i += NTH) {
            int r = i / (BK / 4);
            int c = (i % (BK / 4)) * 4;
            float4 v = make_float4(0.f, 0.f, 0.f, 0.f);
            if (m0 + r < M)
                v = *(const float4*)&A[(size_t)(m0 + r) * K + k0 + c];
            As[c + 0][r] = v.x; As[c + 1][r] = v.y;
            As[c + 2][r] = v.z; As[c + 3][r] = v.w;
        }
#pragma unroll
        for (int i = tid; i < BK * BN / 4; i += NTH) {
            int r = i / (BN / 4);
            int c = (i % (BN / 4)) * 4;
            float4 v = make_float4(0.f, 0.f, 0.f, 0.f);
            if (n0 + c + 4 <= N)
                v = *(const float4*)&W[(size_t)(k0 + r) * N + n0 + c];
            Bs[r][c + 0] = v.x; Bs[r][c + 1] = v.y;
            Bs[r][c + 2] = v.z; Bs[r][c + 3] = v.w;
        }
        __syncthreads();
#pragma unroll
        for (int kk = 0; kk < BK; kk++) {
            float a[TM], b[TN];
#pragma unroll
            for (int i = 0; i < TM; i++) a[i] = As[kk][threadIdx.y * TM + i];
#pragma unroll
            for (int j = 0; j < TN; j++) b[j] = Bs[kk][threadIdx.x * TN + j];
#pragma unroll
            for (int i = 0; i < TM; i++)
#pragma unroll
                for (int j = 0; j < TN; j++) acc[i][j] += a[i] * b[j];
        }
        __syncthreads();
    }
#pragma unroll
    for (int i = 0; i < TM; i++) {
        int m = m0 + threadIdx.y * TM + i;
        if (m >= M) continue;
#pragma unroll
        for (int j = 0; j < TN; j++) {
            int n = n0 + threadIdx.x * TN + j;
            if (n < N) C[(size_t)m * N + n] = acc[i][j] + bias[n];
        }
    }
}

// ---------------- SPMM (feature-tiled) ----------------
template <int DTOT, int LANES, int ROWS, bool RELU, int OUT>
__global__ void k_spmm(const float* __restrict__ s, float* __restrict__ h,
                       __nv_bfloat16* __restrict__ oh, __nv_bfloat16* __restrict__ ol,
                       int c0) {
    int row = blockIdx.x * ROWS + threadIdx.y;
    if (row >= NN) return;
    const int x = c0 + threadIdx.x;
    const float4* s4 = (const float4*)s;
    int e = g_rowptr[row];
    const int end = g_rowptr[row + 1];
    float4 acc = make_float4(0.f, 0.f, 0.f, 0.f);
    for (; e + 1 < end; e += 2) {
        int sc0 = g_srcs[e], sc1 = g_srcs[e + 1];
        float v0 = g_vals[e], v1 = g_vals[e + 1];
        float4 t0 = s4[(size_t)sc0 * (DTOT / 4) + x];
        float4 t1 = s4[(size_t)sc1 * (DTOT / 4) + x];
        acc.x += v0 * t0.x + v1 * t1.x;
        acc.y += v0 * t0.y + v1 * t1.y;
        acc.z += v0 * t0.z + v1 * t1.z;
        acc.w += v0 * t0.w + v1 * t1.w;
    }
    if (e < end) {
        int sc = g_srcs[e];
        float v = g_vals[e];
        float4 t = s4[(size_t)sc * (DTOT / 4) + x];
        acc.x += v * t.x; acc.y += v * t.y; acc.z += v * t.z; acc.w += v * t.w;
    }
    if (RELU) {
        acc.x = fmaxf(acc.x, 0.f); acc.y = fmaxf(acc.y, 0.f);
        acc.z = fmaxf(acc.z, 0.f); acc.w = fmaxf(acc.w, 0.f);
    }
    if (OUT == 0) {
        ((float4*)h)[(size_t)row * (DTOT / 4) + x] = acc;
    } else {
        uint32_t h0, l0, h1, l1;
        split2(acc.x, acc.y, h0, l0);
        split2(acc.z, acc.w, h1, l1);
        ((uint2*)oh)[(size_t)row * (DTOT / 4) + x] = make_uint2(h0, h1);
        ((uint2*)ol)[(size_t)row * (DTOT / 4) + x] = make_uint2(l0, l1);
    }
}

// ---------------- log_softmax ----------------
__global__ void k_lsm(const float* __restrict__ logits, float* __restrict__ out) {
    int row = blockIdx.x * blockDim.y + threadIdx.y;
    if (row >= NN) return;
    const int l = threadIdx.x;
    float a = logits[(size_t)row * 40 + l];
    float b = (l < 8) ? logits[(size_t)row * 40 + 32 + l] : -1e30f;
    float m = fmaxf(a, b);
#pragma unroll
    for (int off = 16; off > 0; off >>= 1)
        m = fmaxf(m, __shfl_xor_sync(0xFFFFFFFFu, m, off));
    float sum = expf(a - m) + ((l < 8) ? expf(b - m) : 0.f);
#pragma unroll
    for (int off = 16; off > 0; off >>= 1)
        sum += __shfl_xor_sync(0xFFFFFFFFu, sum, off);
    float ls = m + logf(sum);
    out[(size_t)row * 40 + l] = a - ls;
    if (l < 8) out[(size_t)row * 40 + 32 + l] = b - ls;
}

// ---------------- launch ----------------
extern "C" void kernel_launch(void* const* d_in, const int* in_sizes, int n_in,
                              void* d_out, int out_size) {
    const float* x    = (const float*)d_in[0];
    const int*   esrc = (const int*)d_in[1];
    const int*   edst = (const int*)d_in[2];
    const float* eval = (const float*)d_in[3];
    const float* W0   = (const float*)d_in[4];
    const float* b0   = (const float*)d_in[5];
    const float* W1   = (const float*)d_in[6];
    const float* b1   = (const float*)d_in[7];
    const float* W2   = (const float*)d_in[8];
    const float* b2   = (const float*)d_in[9];
    float* out = (float*)d_out;

    float *ps, *ph;
    __nv_bfloat16 *pah, *pal, *pw0h, *pw0l, *pw1h, *pw1l;
    cudaGetSymbolAddress((void**)&ps, g_s);
    cudaGetSymbolAddress((void**)&ph, g_h);
    cudaGetSymbolAddress((void**)&pah, g_ah);
    cudaGetSymbolAddress((void**)&pal, g_al);
    cudaGetSymbolAddress((void**)&pw0h, g_w0h);
    cudaGetSymbolAddress((void**)&pw0l, g_w0l);
    cudaGetSymbolAddress((void**)&pw1h, g_w1h);
    cudaGetSymbolAddress((void**)&pw1l, g_w1l);

    static cudaStream_t s2 = nullptr;
    static cudaEvent_t evFork = nullptr, evG0a = nullptr, evG0b = nullptr,
                       evP1 = nullptr, evP2 = nullptr;
    if (s2 == nullptr) {
        cudaStreamCreateWithFlags(&s2, cudaStreamNonBlocking);
        cudaEventCreateWithFlags(&evFork, cudaEventDisableTiming);
        cudaEventCreateWithFlags(&evG0a, cudaEventDisableTiming);
        cudaEventCreateWithFlags(&evG0b, cudaEventDisableTiming);
        cudaEventCreateWithFlags(&evP1, cudaEventDisableTiming);
        cudaEventCreateWithFlags(&evP2, cudaEventDisableTiming);
    }

    const int MB = (NN + 127) / 128;  // 782

    // ---- fork: CSR build on s2 ----
    cudaEventRecord(evFork, 0);
    cudaStreamWaitEvent(s2, evFork, 0);
    k_zero_deg<<<(NN + 255) / 256, 256, 0, s2>>>();
    k_hist<<<(NE + 255) / 256, 256, 0, s2>>>(edst);
    k_scan<<<1, 1024, 0, s2>>>();
    k_scatter<<<(NE + 255) / 256, 256, 0, s2>>>(esrc, edst, eval);

    // ---- stream0: weight conversions, then GEMM0 in two N-halves ----
    k_cvt_w<<<(512 * 256 + 255) / 256, 256>>>(W0, pw0h, pw0l, 512, 256);
    k_cvt_w<<<(256 * 128 + 255) / 256, 256>>>(W1, pw1h, pw1l, 256, 128);

    // GEMM0a: s0 cols [0,128)
    k_mma_gemm_f32a<<<dim3(1, MB), 256>>>(x, pw0h, pw0l, b0, ps, NN, 512, 256, 0);
    cudaEventRecord(evG0a, 0);
    // GEMM0b: s0 cols [128,256)  (runs concurrent with SPMM0 pass1 on s2)
    k_mma_gemm_f32a<<<dim3(1, MB), 256>>>(x, pw0h, pw0l, b0, ps, NN, 512, 256, 128);
    cudaEventRecord(evG0b, 0);

    // ---- s2: SPMM0 feature passes (each needs its GEMM0 half + CSR) ----
    cudaStreamWaitEvent(s2, evG0a, 0);
    k_spmm<256, 32, 8, true, 1><<<(NN + 7) / 8, dim3(32, 8), 0, s2>>>(ps, nullptr, pah, pal, 0);
    cudaEventRecord(evP1, s2);
    cudaStreamWaitEvent(s2, evG0b, 0);
    k_spmm<256, 32, 8, true, 1><<<(NN + 7) / 8, dim3(32, 8), 0, s2>>>(ps, nullptr, pah, pal, 32);
    cudaEventRecord(evP2, s2);

    // ---- stream0: GEMM1 in two K-halves (s1 -> g_h), pipelined with SPMM0 pass2 ----
    cudaStreamWaitEvent(0, evP1, 0);
    k_mma_gemm<<<dim3(1, MB), 256>>>(pah, pal, pw1h, pw1l, b1, ph, NN, 256, 0, 128, 128, 0);
    cudaStreamWaitEvent(0, evP2, 0);
    k_mma_gemm<<<dim3(1, MB), 256>>>(pah, pal, pw1h, pw1l, b1, ph, NN, 256, 128, 128, 128, 1);

    // SPMM1: s1 (g_h) -> h1 (g_s), 2 feature passes
    k_spmm<128, 16, 16, true, 0><<<(NN + 15) / 16, dim3(16, 16)>>>(ph, ps, nullptr, nullptr, 0);
    k_spmm<128, 16, 16, true, 0><<<(NN + 15) / 16, dim3(16, 16)>>>(ph, ps, nullptr, nullptr, 16);

    // Layer 2: s2 = h1 @ W2 + b2 (g_s -> g_h)
    k_gemm<128, 64, 16, 8, 4><<<dim3(1, MB), dim3(16, 16)>>>(ps, W2, b2, ph, NN, 128, 40);
    // SPMM2: logits (g_h -> g_s)
    k_spmm<40, 10, 16, false, 0><<<(NN + 15) / 16, dim3(10, 16)>>>(ph, ps, nullptr, nullptr, 0);

    k_lsm<<<(NN + 7) / 8, dim3(32, 8)>>>(ps, out);
}

// round 10
// speedup vs baseline: 1.2316x; 1.2316x over previous
#include <cuda_runtime.h>
#include <cuda_bf16.h>
#include <math.h>
#include <stdint.h>

#define NN 100000
#define NE 3200000

// ---------------- scratch ----------------
__device__ float g_s[(size_t)NN * 256];
__device__ float g_h[(size_t)NN * 256];
__device__ __nv_bfloat16 g_ah[(size_t)NN * 256];   // activation hi
__device__ __nv_bfloat16 g_al[(size_t)NN * 256];   // activation lo
__device__ __nv_bfloat16 g_w0h[512 * 256], g_w0l[512 * 256];   // [N][K] n-major
__device__ __nv_bfloat16 g_w1h[256 * 128], g_w1l[256 * 128];
__device__ __nv_bfloat16 g_w2h[64 * 128],  g_w2l[64 * 128];    // N padded 40->64
__device__ int   g_deg[NN];
__device__ int   g_rowptr[NN + 1];
__device__ int   g_cursor[NN];
__device__ int   g_srcs[NE];
__device__ float g_vals[NE];

// ---------------- helpers ----------------
__device__ __forceinline__ uint32_t smem_u32(const void* p) {
    uint32_t a;
    asm("{ .reg .u64 t; cvta.to.shared.u64 t, %1; cvt.u32.u64 %0, t; }" : "=r"(a) : "l"(p));
    return a;
}

__device__ __forceinline__ void split2(float a, float b, uint32_t& hi, uint32_t& lo) {
    __nv_bfloat16 ah = __float2bfloat16(a), bh = __float2bfloat16(b);
    float ar = a - __bfloat162float(ah);
    float br = b - __bfloat162float(bh);
    __nv_bfloat16 al = __float2bfloat16(ar), bl = __float2bfloat16(br);
    hi = (uint32_t)__bfloat16_as_ushort(ah) | ((uint32_t)__bfloat16_as_ushort(bh) << 16);
    lo = (uint32_t)__bfloat16_as_ushort(al) | ((uint32_t)__bfloat16_as_ushort(bl) << 16);
}

__device__ __forceinline__ void ldm4(uint32_t* r, uint32_t addr) {
    asm volatile("ldmatrix.sync.aligned.m8n8.x4.shared.b16 {%0,%1,%2,%3}, [%4];"
                 : "=r"(r[0]), "=r"(r[1]), "=r"(r[2]), "=r"(r[3]) : "r"(addr));
}

__device__ __forceinline__ void mma16816(float* c, const uint32_t* a, uint32_t b0, uint32_t b1) {
    asm volatile(
        "mma.sync.aligned.m16n8k16.row.col.f32.bf16.bf16.f32 "
        "{%0,%1,%2,%3}, {%4,%5,%6,%7}, {%8,%9}, {%0,%1,%2,%3};"
        : "+f"(c[0]), "+f"(c[1]), "+f"(c[2]), "+f"(c[3])
        : "r"(a[0]), "r"(a[1]), "r"(a[2]), "r"(a[3]), "r"(b0), "r"(b1));
}

// ---------------- CSR build ----------------
__global__ void k_zero_deg() {
    int i = blockIdx.x * blockDim.x + threadIdx.x;
    if (i < NN) g_deg[i] = 0;
}
__global__ void k_hist(const int* __restrict__ dst) {
    int e = blockIdx.x * blockDim.x + threadIdx.x;
    if (e < NE) atomicAdd(&g_deg[dst[e]], 1);
}
__global__ void k_scan() {
    __shared__ int ssum[1024];
    const int t = threadIdx.x;
    const int CH = (NN + 1023) / 1024;
    int s0 = t * CH, s1 = s0 + CH; if (s1 > NN) s1 = NN;
    int sum = 0;
    for (int i = s0; i < s1; i++) sum += g_deg[i];
    ssum[t] = sum;
    __syncthreads();
    for (int off = 1; off < 1024; off <<= 1) {
        int v = (t >= off) ? ssum[t - off] : 0;
        __syncthreads();
        ssum[t] += v;
        __syncthreads();
    }
    int run = (t == 0) ? 0 : ssum[t - 1];
    for (int i = s0; i < s1; i++) { g_rowptr[i] = run; g_cursor[i] = run; run += g_deg[i]; }
    if (t == 1023) g_rowptr[NN] = ssum[1023];
}
__global__ void k_scatter(const int* __restrict__ src, const int* __restrict__ dst,
                          const float* __restrict__ val) {
    int e = blockIdx.x * blockDim.x + threadIdx.x;
    if (e >= NE) return;
    int d = dst[e];
    int p = atomicAdd(&g_cursor[d], 1);
    g_srcs[p] = src[e];
    g_vals[p] = val[e];
}

// ---------------- weight converters ----------------
__global__ void k_cvt_w(const float* __restrict__ W, __nv_bfloat16* __restrict__ wh,
                        __nv_bfloat16* __restrict__ wl, int K, int N) {
    int idx = blockIdx.x * blockDim.x + threadIdx.x;
    if (idx >= N * K) return;
    int n = idx / K, k = idx % K;
    float v = W[(size_t)k * N + n];
    __nv_bfloat16 h = __float2bfloat16(v);
    float r = v - __bfloat162float(h);
    wh[idx] = h;
    wl[idx] = __float2bfloat16(r);
}
// padded: rows [N, Npad) are zero
__global__ void k_cvt_w_pad(const float* __restrict__ W, __nv_bfloat16* __restrict__ wh,
                            __nv_bfloat16* __restrict__ wl, int K, int N, int Npad) {
    int idx = blockIdx.x * blockDim.x + threadIdx.x;
    if (idx >= Npad * K) return;
    int n = idx / K, k = idx % K;
    float v = (n < N) ? W[(size_t)k * N + n] : 0.f;
    __nv_bfloat16 h = __float2bfloat16(v);
    float r = v - __bfloat162float(h);
    wh[idx] = h;
    wl[idx] = __float2bfloat16(r);
}

// ---------------- tensor-core GEMM (fp32 A, fused split): C = A @ B^T + bias ----------------
__global__ void __launch_bounds__(256, 2)
k_mma_gemm_f32a(const float* __restrict__ A,
                const __nv_bfloat16* __restrict__ Bh, const __nv_bfloat16* __restrict__ Bl,
                const float* __restrict__ bias, float* __restrict__ C,
                int M, int K, int N) {
    __shared__ __nv_bfloat16 sAh[128][40];
    __shared__ __nv_bfloat16 sAl[128][40];
    __shared__ __nv_bfloat16 sBh[128][40];
    __shared__ __nv_bfloat16 sBl[128][40];

    const int tid = threadIdx.x;
    const int wid = tid >> 5, lane = tid & 31;
    const int m0 = blockIdx.y * 128;
    const int n0 = blockIdx.x * 128;
    const int wm = wid >> 2;
    const int wn = wid & 3;

    int lrow[2], lq[2];
#pragma unroll
    for (int it = 0; it < 2; it++) {
        int idx = it * 256 + tid;
        lrow[it] = idx >> 2;
        lq[it] = idx & 3;
    }

    float acc[4][4][4];
#pragma unroll
    for (int a = 0; a < 4; a++)
#pragma unroll
        for (int b = 0; b < 4; b++)
#pragma unroll
            for (int c = 0; c < 4; c++) acc[a][b][c] = 0.f;

    float4 fA[2][2];
    uint4 pBh[2], pBl[2];

    auto fetch = [&](int ch) {
        const int k0 = ch * 32;
#pragma unroll
        for (int it = 0; it < 2; it++) {
            int row = lrow[it], q = lq[it];
            if (m0 + row < M) {
                const float* p = &A[(size_t)(m0 + row) * K + k0 + q * 8];
                fA[it][0] = *(const float4*)p;
                fA[it][1] = *(const float4*)(p + 4);
            } else {
                fA[it][0] = make_float4(0.f, 0.f, 0.f, 0.f);
                fA[it][1] = make_float4(0.f, 0.f, 0.f, 0.f);
            }
            size_t offb = (size_t)(n0 + row) * K + k0 + q * 8;
            pBh[it] = *(const uint4*)&Bh[offb];
            pBl[it] = *(const uint4*)&Bl[offb];
        }
    };
    auto commit = [&]() {
#pragma unroll
        for (int it = 0; it < 2; it++) {
            int row = lrow[it], q = lq[it];
            uint4 vh, vl;
            split2(fA[it][0].x, fA[it][0].y, vh.x, vl.x);
            split2(fA[it][0].z, fA[it][0].w, vh.y, vl.y);
            split2(fA[it][1].x, fA[it][1].y, vh.z, vl.z);
            split2(fA[it][1].z, fA[it][1].w, vh.w, vl.w);
            *(uint4*)&sAh[row][q * 8] = vh;
            *(uint4*)&sAl[row][q * 8] = vl;
            *(uint4*)&sBh[row][q * 8] = pBh[it];
            *(uint4*)&sBl[row][q * 8] = pBl[it];
        }
    };

    const int nch = K / 32;
    fetch(0);
    commit();

    for (int ch = 0; ch < nch; ch++) {
        __syncthreads();
        if (ch + 1 < nch) fetch(ch + 1);

#pragma unroll
        for (int kk = 0; kk < 32; kk += 16) {
            const int r = lane & 15;
            const int koff = (lane >> 4) << 3;
            uint32_t bhf[2][4], blf[2][4];
#pragma unroll
            for (int nt = 0; nt < 2; nt++) {
                ldm4(bhf[nt], smem_u32(&sBh[wn * 32 + nt * 16 + r][kk + koff]));
                ldm4(blf[nt], smem_u32(&sBl[wn * 32 + nt * 16 + r][kk + koff]));
            }
#pragma unroll
            for (int mt = 0; mt < 4; mt++) {
                uint32_t af[4];
                ldm4(af, smem_u32(&sAh[wm * 64 + mt * 16 + r][kk + koff]));
#pragma unroll
                for (int j = 0; j < 4; j++) {
                    mma16816(acc[mt][j], af, bhf[j >> 1][j & 1], bhf[j >> 1][2 + (j & 1)]);
                    mma16816(acc[mt][j], af, blf[j >> 1][j & 1], blf[j >> 1][2 + (j & 1)]);
                }
            }
#pragma unroll
            for (int mt = 0; mt < 4; mt++) {
                uint32_t af[4];
                ldm4(af, smem_u32(&sAl[wm * 64 + mt * 16 + r][kk + koff]));
#pragma unroll
                for (int j = 0; j < 4; j++)
                    mma16816(acc[mt][j], af, bhf[j >> 1][j & 1], bhf[j >> 1][2 + (j & 1)]);
            }
        }
        __syncthreads();
        if (ch + 1 < nch) commit();
    }

    const int rbase = m0 + wm * 64 + (lane >> 2);
    const int cbase = n0 + wn * 32 + (lane & 3) * 2;
#pragma unroll
    for (int mt = 0; mt < 4; mt++) {
        int m = rbase + mt * 16;
#pragma unroll
        for (int j = 0; j < 4; j++) {
            int c = cbase + j * 8;
            float bv0 = bias[c], bv1 = bias[c + 1];
            if (m < M) {
                float2 o = make_float2(acc[mt][j][0] + bv0, acc[mt][j][1] + bv1);
                *(float2*)&C[(size_t)m * N + c] = o;
            }
            if (m + 8 < M) {
                float2 o = make_float2(acc[mt][j][2] + bv0, acc[mt][j][3] + bv1);
                *(float2*)&C[(size_t)(m + 8) * N + c] = o;
            }
        }
    }
}

// ---------------- tensor-core GEMM (bf16 hi/lo A): C = A @ B^T + bias ----------------
__global__ void __launch_bounds__(256, 2)
k_mma_gemm(const __nv_bfloat16* __restrict__ Ah, const __nv_bfloat16* __restrict__ Al,
           const __nv_bfloat16* __restrict__ Bh, const __nv_bfloat16* __restrict__ Bl,
           const float* __restrict__ bias, float* __restrict__ C,
           int M, int K, int N) {
    __shared__ __nv_bfloat16 sAh[128][40];
    __shared__ __nv_bfloat16 sAl[128][40];
    __shared__ __nv_bfloat16 sBh[128][40];
    __shared__ __nv_bfloat16 sBl[128][40];

    const int tid = threadIdx.x;
    const int wid = tid >> 5, lane = tid & 31;
    const int m0 = blockIdx.y * 128;
    const int n0 = blockIdx.x * 128;
    const int wm = wid >> 2;
    const int wn = wid & 3;

    int lrow[2], lq[2];
#pragma unroll
    for (int it = 0; it < 2; it++) {
        int idx = it * 256 + tid;
        lrow[it] = idx >> 2;
        lq[it] = idx & 3;
    }

    float acc[4][4][4];
#pragma unroll
    for (int a = 0; a < 4; a++)
#pragma unroll
        for (int b = 0; b < 4; b++)
#pragma unroll
            for (int c = 0; c < 4; c++) acc[a][b][c] = 0.f;

    uint4 pAh[2], pAl[2], pBh[2], pBl[2];

    auto fetch = [&](int ch) {
        const int k0 = ch * 32;
#pragma unroll
        for (int it = 0; it < 2; it++) {
            int row = lrow[it], q = lq[it];
            if (m0 + row < M) {
                size_t off = (size_t)(m0 + row) * K + k0 + q * 8;
                pAh[it] = *(const uint4*)&Ah[off];
                pAl[it] = *(const uint4*)&Al[off];
            } else {
                pAh[it] = make_uint4(0, 0, 0, 0);
                pAl[it] = make_uint4(0, 0, 0, 0);
            }
            size_t offb = (size_t)(n0 + row) * K + k0 + q * 8;
            pBh[it] = *(const uint4*)&Bh[offb];
            pBl[it] = *(const uint4*)&Bl[offb];
        }
    };
    auto commit = [&]() {
#pragma unroll
        for (int it = 0; it < 2; it++) {
            int row = lrow[it], q = lq[it];
            *(uint4*)&sAh[row][q * 8] = pAh[it];
            *(uint4*)&sAl[row][q * 8] = pAl[it];
            *(uint4*)&sBh[row][q * 8] = pBh[it];
            *(uint4*)&sBl[row][q * 8] = pBl[it];
        }
    };

    const int nch = K / 32;
    fetch(0);
    commit();

    for (int ch = 0; ch < nch; ch++) {
        __syncthreads();
        if (ch + 1 < nch) fetch(ch + 1);

#pragma unroll
        for (int kk = 0; kk < 32; kk += 16) {
            const int r = lane & 15;
            const int koff = (lane >> 4) << 3;
            uint32_t bhf[2][4], blf[2][4];
#pragma unroll
            for (int nt = 0; nt < 2; nt++) {
                ldm4(bhf[nt], smem_u32(&sBh[wn * 32 + nt * 16 + r][kk + koff]));
                ldm4(blf[nt], smem_u32(&sBl[wn * 32 + nt * 16 + r][kk + koff]));
            }
#pragma unroll
            for (int mt = 0; mt < 4; mt++) {
                uint32_t af[4];
                ldm4(af, smem_u32(&sAh[wm * 64 + mt * 16 + r][kk + koff]));
#pragma unroll
                for (int j = 0; j < 4; j++) {
                    mma16816(acc[mt][j], af, bhf[j >> 1][j & 1], bhf[j >> 1][2 + (j & 1)]);
                    mma16816(acc[mt][j], af, blf[j >> 1][j & 1], blf[j >> 1][2 + (j & 1)]);
                }
            }
#pragma unroll
            for (int mt = 0; mt < 4; mt++) {
                uint32_t af[4];
                ldm4(af, smem_u32(&sAl[wm * 64 + mt * 16 + r][kk + koff]));
#pragma unroll
                for (int j = 0; j < 4; j++)
                    mma16816(acc[mt][j], af, bhf[j >> 1][j & 1], bhf[j >> 1][2 + (j & 1)]);
            }
        }
        __syncthreads();
        if (ch + 1 < nch) commit();
    }

    const int rbase = m0 + wm * 64 + (lane >> 2);
    const int cbase = n0 + wn * 32 + (lane & 3) * 2;
#pragma unroll
    for (int mt = 0; mt < 4; mt++) {
        int m = rbase + mt * 16;
#pragma unroll
        for (int j = 0; j < 4; j++) {
            int c = cbase + j * 8;
            float bv0 = bias[c], bv1 = bias[c + 1];
            if (m < M) {
                float2 o = make_float2(acc[mt][j][0] + bv0, acc[mt][j][1] + bv1);
                *(float2*)&C[(size_t)m * N + c] = o;
            }
            if (m + 8 < M) {
                float2 o = make_float2(acc[mt][j][2] + bv0, acc[mt][j][3] + bv1);
                *(float2*)&C[(size_t)(m + 8) * N + c] = o;
            }
        }
    }
}

// ---------------- tensor-core GEMM, layer 2: K=128, Npad=64, Nout=40 ----------------
// A: [M][128] bf16 hi/lo. B: [64][128] bf16 hi/lo (zero-padded). C: [M][40] fp32.
// 8 warps: 4m x 2n, warp tile 32x32.
__global__ void __launch_bounds__(256, 2)
k_mma_gemm64(const __nv_bfloat16* __restrict__ Ah, const __nv_bfloat16* __restrict__ Al,
             const __nv_bfloat16* __restrict__ Bh, const __nv_bfloat16* __restrict__ Bl,
             const float* __restrict__ bias, float* __restrict__ C, int M) {
    const int K = 128, NOUT = 40;
    __shared__ __nv_bfloat16 sAh[128][40];
    __shared__ __nv_bfloat16 sAl[128][40];
    __shared__ __nv_bfloat16 sBh[64][40];
    __shared__ __nv_bfloat16 sBl[64][40];

    const int tid = threadIdx.x;
    const int wid = tid >> 5, lane = tid & 31;
    const int m0 = blockIdx.y * 128;
    const int wm = wid >> 1;   // 0..3, 32 rows
    const int wn = wid & 1;    // 0..1, 32 cols

    int lrowA[2], lqA[2];
#pragma unroll
    for (int it = 0; it < 2; it++) {
        int idx = it * 256 + tid;
        lrowA[it] = idx >> 2;
        lqA[it] = idx & 3;
    }
    const int lrowB = tid >> 2, lqB = tid & 3;   // 64 rows x 4 quads

    float acc[2][4][4];
#pragma unroll
    for (int a = 0; a < 2; a++)
#pragma unroll
        for (int b = 0; b < 4; b++)
#pragma unroll
            for (int c = 0; c < 4; c++) acc[a][b][c] = 0.f;

    uint4 pAh[2], pAl[2], pBh1, pBl1;

    auto fetch = [&](int ch) {
        const int k0 = ch * 32;
#pragma unroll
        for (int it = 0; it < 2; it++) {
            int row = lrowA[it], q = lqA[it];
            if (m0 + row < M) {
                size_t off = (size_t)(m0 + row) * K + k0 + q * 8;
                pAh[it] = *(const uint4*)&Ah[off];
                pAl[it] = *(const uint4*)&Al[off];
            } else {
                pAh[it] = make_uint4(0, 0, 0, 0);
                pAl[it] = make_uint4(0, 0, 0, 0);
            }
        }
        size_t offb = (size_t)lrowB * K + k0 + lqB * 8;
        pBh1 = *(const uint4*)&Bh[offb];
        pBl1 = *(const uint4*)&Bl[offb];
    };
    auto commit = [&]() {
#pragma unroll
        for (int it = 0; it < 2; it++) {
            int row = lrowA[it], q = lqA[it];
            *(uint4*)&sAh[row][q * 8] = pAh[it];
            *(uint4*)&sAl[row][q * 8] = pAl[it];
        }
        *(uint4*)&sBh[lrowB][lqB * 8] = pBh1;
        *(uint4*)&sBl[lrowB][lqB * 8] = pBl1;
    };

    const int nch = K / 32;   // 4
    fetch(0);
    commit();

    for (int ch = 0; ch < nch; ch++) {
        __syncthreads();
        if (ch + 1 < nch) fetch(ch + 1);

#pragma unroll
        for (int kk = 0; kk < 32; kk += 16) {
            const int r = lane & 15;
            const int koff = (lane >> 4) << 3;
            uint32_t bhf[2][4], blf[2][4];
#pragma unroll
            for (int nt = 0; nt < 2; nt++) {
                ldm4(bhf[nt], smem_u32(&sBh[wn * 32 + nt * 16 + r][kk + koff]));
                ldm4(blf[nt], smem_u32(&sBl[wn * 32 + nt * 16 + r][kk + koff]));
            }
#pragma unroll
            for (int mt = 0; mt < 2; mt++) {
                uint32_t af[4];
                ldm4(af, smem_u32(&sAh[wm * 32 + mt * 16 + r][kk + koff]));
#pragma unroll
                for (int j = 0; j < 4; j++) {
                    mma16816(acc[mt][j], af, bhf[j >> 1][j & 1], bhf[j >> 1][2 + (j & 1)]);
                    mma16816(acc[mt][j], af, blf[j >> 1][j & 1], blf[j >> 1][2 + (j & 1)]);
                }
            }
#pragma unroll
            for (int mt = 0; mt < 2; mt++) {
                uint32_t af[4];
                ldm4(af, smem_u32(&sAl[wm * 32 + mt * 16 + r][kk + koff]));
#pragma unroll
                for (int j = 0; j < 4; j++)
                    mma16816(acc[mt][j], af, bhf[j >> 1][j & 1], bhf[j >> 1][2 + (j & 1)]);
            }
        }
        __syncthreads();
        if (ch + 1 < nch) commit();
    }

    const int rbase = m0 + wm * 32 + (lane >> 2);
    const int cbase = wn * 32 + (lane & 3) * 2;
#pragma unroll
    for (int mt = 0; mt < 2; mt++) {
        int m = rbase + mt * 16;
#pragma unroll
        for (int j = 0; j < 4; j++) {
            int c = cbase + j * 8;
            if (c >= NOUT) continue;
            float bv0 = bias[c], bv1 = bias[c + 1];
            if (m < M) {
                float2 o = make_float2(acc[mt][j][0] + bv0, acc[mt][j][1] + bv1);
                *(float2*)&C[(size_t)m * NOUT + c] = o;
            }
            if (m + 8 < M) {
                float2 o = make_float2(acc[mt][j][2] + bv0, acc[mt][j][3] + bv1);
                *(float2*)&C[(size_t)(m + 8) * NOUT + c] = o;
            }
        }
    }
}

// ---------------- SPMM (feature-tiled) ----------------
template <int DTOT, int LANES, int ROWS, bool RELU, int OUT>
__global__ void k_spmm(const float* __restrict__ s, float* __restrict__ h,
                       __nv_bfloat16* __restrict__ oh, __nv_bfloat16* __restrict__ ol,
                       int c0) {
    int row = blockIdx.x * ROWS + threadIdx.y;
    if (row >= NN) return;
    const int x = c0 + threadIdx.x;
    const float4* s4 = (const float4*)s;
    int e = g_rowptr[row];
    const int end = g_rowptr[row + 1];
    float4 acc = make_float4(0.f, 0.f, 0.f, 0.f);
    for (; e + 1 < end; e += 2) {
        int sc0 = g_srcs[e], sc1 = g_srcs[e + 1];
        float v0 = g_vals[e], v1 = g_vals[e + 1];
        float4 t0 = s4[(size_t)sc0 * (DTOT / 4) + x];
        float4 t1 = s4[(size_t)sc1 * (DTOT / 4) + x];
        acc.x += v0 * t0.x + v1 * t1.x;
        acc.y += v0 * t0.y + v1 * t1.y;
        acc.z += v0 * t0.z + v1 * t1.z;
        acc.w += v0 * t0.w + v1 * t1.w;
    }
    if (e < end) {
        int sc = g_srcs[e];
        float v = g_vals[e];
        float4 t = s4[(size_t)sc * (DTOT / 4) + x];
        acc.x += v * t.x; acc.y += v * t.y; acc.z += v * t.z; acc.w += v * t.w;
    }
    if (RELU) {
        acc.x = fmaxf(acc.x, 0.f); acc.y = fmaxf(acc.y, 0.f);
        acc.z = fmaxf(acc.z, 0.f); acc.w = fmaxf(acc.w, 0.f);
    }
    if (OUT == 0) {
        ((float4*)h)[(size_t)row * (DTOT / 4) + x] = acc;
    } else {
        uint32_t h0, l0, h1, l1;
        split2(acc.x, acc.y, h0, l0);
        split2(acc.z, acc.w, h1, l1);
        ((uint2*)oh)[(size_t)row * (DTOT / 4) + x] = make_uint2(h0, h1);
        ((uint2*)ol)[(size_t)row * (DTOT / 4) + x] = make_uint2(l0, l1);
    }
}

// ---------------- log_softmax ----------------
__global__ void k_lsm(const float* __restrict__ logits, float* __restrict__ out) {
    int row = blockIdx.x * blockDim.y + threadIdx.y;
    if (row >= NN) return;
    const int l = threadIdx.x;
    float a = logits[(size_t)row * 40 + l];
    float b = (l < 8) ? logits[(size_t)row * 40 + 32 + l] : -1e30f;
    float m = fmaxf(a, b);
#pragma unroll
    for (int off = 16; off > 0; off >>= 1)
        m = fmaxf(m, __shfl_xor_sync(0xFFFFFFFFu, m, off));
    float sum = expf(a - m) + ((l < 8) ? expf(b - m) : 0.f);
#pragma unroll
    for (int off = 16; off > 0; off >>= 1)
        sum += __shfl_xor_sync(0xFFFFFFFFu, sum, off);
    float ls = m + logf(sum);
    out[(size_t)row * 40 + l] = a - ls;
    if (l < 8) out[(size_t)row * 40 + 32 + l] = b - ls;
}

// ---------------- launch ----------------
extern "C" void kernel_launch(void* const* d_in, const int* in_sizes, int n_in,
                              void* d_out, int out_size) {
    const float* x    = (const float*)d_in[0];
    const int*   esrc = (const int*)d_in[1];
    const int*   edst = (const int*)d_in[2];
    const float* eval = (const float*)d_in[3];
    const float* W0   = (const float*)d_in[4];
    const float* b0   = (const float*)d_in[5];
    const float* W1   = (const float*)d_in[6];
    const float* b1   = (const float*)d_in[7];
    const float* W2   = (const float*)d_in[8];
    const float* b2   = (const float*)d_in[9];
    float* out = (float*)d_out;

    float *ps, *ph;
    __nv_bfloat16 *pah, *pal, *pw0h, *pw0l, *pw1h, *pw1l, *pw2h, *pw2l;
    cudaGetSymbolAddress((void**)&ps, g_s);
    cudaGetSymbolAddress((void**)&ph, g_h);
    cudaGetSymbolAddress((void**)&pah, g_ah);
    cudaGetSymbolAddress((void**)&pal, g_al);
    cudaGetSymbolAddress((void**)&pw0h, g_w0h);
    cudaGetSymbolAddress((void**)&pw0l, g_w0l);
    cudaGetSymbolAddress((void**)&pw1h, g_w1h);
    cudaGetSymbolAddress((void**)&pw1l, g_w1l);
    cudaGetSymbolAddress((void**)&pw2h, g_w2h);
    cudaGetSymbolAddress((void**)&pw2l, g_w2l);

    static cudaStream_t s2 = nullptr;
    static cudaEvent_t evFork = nullptr, evCsr = nullptr;
    if (s2 == nullptr) {
        cudaStreamCreateWithFlags(&s2, cudaStreamNonBlocking);
        cudaEventCreateWithFlags(&evFork, cudaEventDisableTiming);
        cudaEventCreateWithFlags(&evCsr, cudaEventDisableTiming);
    }

    // fork: CSR build on s2, concurrent with cvt_w + GEMM0
    cudaEventRecord(evFork, 0);
    cudaStreamWaitEvent(s2, evFork, 0);
    k_zero_deg<<<(NN + 255) / 256, 256, 0, s2>>>();
    k_hist<<<(NE + 255) / 256, 256, 0, s2>>>(edst);
    k_scan<<<1, 1024, 0, s2>>>();
    k_scatter<<<(NE + 255) / 256, 256, 0, s2>>>(esrc, edst, eval);
    cudaEventRecord(evCsr, s2);

    // main stream: weight conversions + layer-0 GEMM (A split fused in-kernel)
    k_cvt_w<<<(512 * 256 + 255) / 256, 256>>>(W0, pw0h, pw0l, 512, 256);
    k_cvt_w<<<(256 * 128 + 255) / 256, 256>>>(W1, pw1h, pw1l, 256, 128);
    k_cvt_w_pad<<<(64 * 128 + 255) / 256, 256>>>(W2, pw2h, pw2l, 128, 40, 64);

    const int MB = (NN + 127) / 128;  // 782

    // Layer 0: s0 = x @ W0 + b0 (K=512, N=256), fp32 A with fused hi/lo split
    k_mma_gemm_f32a<<<dim3(2, MB), 256>>>(x, pw0h, pw0l, b0, ps, NN, 512, 256);

    // join: SPMM needs the CSR
    cudaStreamWaitEvent(0, evCsr, 0);

    // SPMM0 + relu -> bf16 hi/lo (2 feature passes of 128 cols)
    k_spmm<256, 32, 8, true, 1><<<(NN + 7) / 8, dim3(32, 8)>>>(ps, nullptr, pah, pal, 0);
    k_spmm<256, 32, 8, true, 1><<<(NN + 7) / 8, dim3(32, 8)>>>(ps, nullptr, pah, pal, 32);

    // Layer 1: s1 = h0 @ W1 + b1 (K=256, N=128) -> ps
    k_mma_gemm<<<dim3(1, MB), 256>>>(pah, pal, pw1h, pw1l, b1, ps, NN, 256, 128);

    // SPMM1 + relu -> bf16 hi/lo (2 feature passes of 64 cols) -> pah/pal
    k_spmm<128, 16, 16, true, 1><<<(NN + 15) / 16, dim3(16, 16)>>>(ps, nullptr, pah, pal, 0);
    k_spmm<128, 16, 16, true, 1><<<(NN + 15) / 16, dim3(16, 16)>>>(ps, nullptr, pah, pal, 16);

    // Layer 2: s2 = h1 @ W2 + b2 (K=128, N=40 padded to 64) tensor cores -> ph
    k_mma_gemm64<<<dim3(1, MB), 256>>>(pah, pal, pw2h, pw2l, b2, ph, NN);

    // SPMM2: logits -> ps
    k_spmm<40, 10, 16, false, 0><<<(NN + 15) / 16, dim3(10, 16)>>>(ph, ps, nullptr, nullptr, 0);

    k_lsm<<<(NN + 7) / 8, dim3(32, 8)>>>(ps, out);
}